// round 11
// baseline (speedup 1.0000x reference)
#include <cuda_runtime.h>
#include <cuda_bf16.h>
#include <cstdint>
#include <math.h>

// Shapes: B=8, S=4096, D=1024, H=16, K=256, DH=64
// R11: pre-split bf16 operands + cp.async double-buffered GEMM mainloop.

// ---------------- device scratch ----------------
__device__ int   g_len[8];
__device__ float g_inv[8];
__device__ float g_cp[2 * 8 * 256];
__device__ __align__(16) uint16_t g_hs_h[(size_t)8 * 4096 * 1024];
__device__ __align__(16) uint16_t g_hs_l[(size_t)8 * 4096 * 1024];
__device__ __align__(16) uint16_t g_p_h[2 * 4096 * 256];
__device__ __align__(16) uint16_t g_p_l[2 * 4096 * 256];
__device__ __align__(16) uint16_t g_w_h[3 * 1024 * 1024];
__device__ __align__(16) uint16_t g_w_l[3 * 1024 * 1024];
__device__ __align__(16) uint16_t g_hp_h[(size_t)2 * 8 * 256 * 1024];
__device__ __align__(16) uint16_t g_hp_l[(size_t)2 * 8 * 256 * 1024];
__device__ __align__(16) uint16_t g_q_h[(size_t)8 * 16 * 4096 * 64];
__device__ __align__(16) uint16_t g_q_l[(size_t)8 * 16 * 4096 * 64];
__device__ __align__(16) uint16_t g_k_h[(size_t)8 * 16 * 256 * 64];
__device__ __align__(16) uint16_t g_k_l[(size_t)8 * 16 * 256 * 64];
__device__ __align__(16) uint16_t g_v_h[(size_t)8 * 16 * 256 * 64];
__device__ __align__(16) uint16_t g_v_l[(size_t)8 * 16 * 256 * 64];

// ---------------- helpers ----------------
__device__ __forceinline__ uint32_t smem_u32(const void* p) {
    uint32_t a;
    asm("{ .reg .u64 t; cvta.to.shared.u64 t, %1; cvt.u32.u64 %0, t; }" : "=r"(a) : "l"(p));
    return a;
}
__device__ __forceinline__ void ldsm_x4(uint32_t& r0, uint32_t& r1, uint32_t& r2, uint32_t& r3,
                                        uint32_t addr) {
    asm volatile("ldmatrix.sync.aligned.m8n8.x4.shared.b16 {%0,%1,%2,%3}, [%4];"
                 : "=r"(r0), "=r"(r1), "=r"(r2), "=r"(r3) : "r"(addr));
}
__device__ __forceinline__ void mma_bf16(float* c, const uint32_t* a, uint32_t b0, uint32_t b1) {
    asm volatile(
        "mma.sync.aligned.m16n8k16.row.col.f32.bf16.bf16.f32 "
        "{%0,%1,%2,%3}, {%4,%5,%6,%7}, {%8,%9}, {%0,%1,%2,%3};"
        : "+f"(c[0]), "+f"(c[1]), "+f"(c[2]), "+f"(c[3])
        : "r"(a[0]), "r"(a[1]), "r"(a[2]), "r"(a[3]), "r"(b0), "r"(b1));
}
__device__ __forceinline__ void split_pack(float x, float y, uint32_t& h, uint32_t& l) {
    __nv_bfloat162 hv = __floats2bfloat162_rn(x, y);
    float hx = __bfloat162float(__low2bfloat16(hv));
    float hy = __bfloat162float(__high2bfloat16(hv));
    __nv_bfloat162 lv = __floats2bfloat162_rn(x - hx, y - hy);
    h = *reinterpret_cast<uint32_t*>(&hv);
    l = *reinterpret_cast<uint32_t*>(&lv);
}

#define CP_ASYNC16(dst, src) \
    asm volatile("cp.async.ca.shared.global [%0], [%1], 16;" :: "r"(dst), "l"(src) : "memory")
#define CP_COMMIT()  asm volatile("cp.async.commit_group;" ::: "memory")
#define CP_WAIT1()   asm volatile("cp.async.wait_group 1;" ::: "memory")
#define CP_WAIT0()   asm volatile("cp.async.wait_group 0;" ::: "memory")

static constexpr int LDT = 40;          // GEMM smem row stride (bf16)
static constexpr int MAT_BYTES = 10240; // 128 * LDT * 2
static constexpr int BUF_BYTES = 4 * MAT_BYTES;       // Ah,Al,Bh,Bl
static constexpr int SMEM_GEMM = 2 * BUF_BYTES;       // 81920

// ---------------- conv: fp32 -> bf16 hi/lo ----------------
__global__ void conv_kernel(const float4* __restrict__ src, int which, int n4) {
    int i = blockIdx.x * blockDim.x + threadIdx.x;
    if (i >= n4) return;
    uint2* dh; uint2* dl;
    switch (which) {
        case 0: dh = (uint2*)g_hs_h; dl = (uint2*)g_hs_l; break;
        case 1: dh = (uint2*)g_p_h;  dl = (uint2*)g_p_l;  break;
        case 2: dh = (uint2*)(g_p_h + 1048576); dl = (uint2*)(g_p_l + 1048576); break;
        case 3: dh = (uint2*)g_w_h;  dl = (uint2*)g_w_l;  break;
        case 4: dh = (uint2*)(g_w_h + 1048576); dl = (uint2*)(g_w_l + 1048576); break;
        default: dh = (uint2*)(g_w_h + 2097152); dl = (uint2*)(g_w_l + 2097152); break;
    }
    float4 a = src[i];
    uint32_t h0, l0, h1, l1;
    split_pack(a.x, a.y, h0, l0);
    split_pack(a.z, a.w, h1, l1);
    dh[i] = make_uint2(h0, h1);
    dl[i] = make_uint2(l0, l1);
}

// ---------------- GEMM: cp.async loader + split-mma compute ----------------
__device__ __forceinline__ void load_chunk_async(uint32_t bufBase, int e0, int tid,
                                                 const uint16_t* Ah, const uint16_t* Al,
                                                 const uint16_t* Bh, const uint16_t* Bl,
                                                 int row0, int col0) {
    #pragma unroll
    for (int j = 0; j < 8; j++) {
        const uint16_t* sp = (j < 2) ? Ah : (j < 4) ? Al : (j < 6) ? Bh : Bl;
        int br = (j < 4) ? row0 : col0;
        int s = ((j & 1) << 8) + tid;
        int r = s >> 2, cs = (s & 3) * 8;
        uint32_t dst = bufBase + (uint32_t)((j >> 1) * MAT_BYTES) + (uint32_t)((r * LDT + cs) * 2);
        const void* src = sp + (size_t)(br + r) * 1024 + e0 + cs;
        CP_ASYNC16(dst, src);
    }
}

__device__ __forceinline__ void compute_chunk(uint32_t bufBase, int wrow, int wcol,
                                              uint32_t laneOff, float acc[4][4][4]) {
    uint32_t AhU = bufBase, AlU = bufBase + MAT_BYTES;
    uint32_t BhU = bufBase + 2 * MAT_BYTES, BlU = bufBase + 3 * MAT_BYTES;
    #pragma unroll
    for (int ks = 0; ks < 32; ks += 16) {
        uint32_t aH[4][4], aL[4][4], bH[4][2], bL[4][2];
        #pragma unroll
        for (int rt = 0; rt < 4; rt++) {
            uint32_t off = (uint32_t)(((wrow + rt * 16) * LDT + ks) * 2) + laneOff;
            ldsm_x4(aH[rt][0], aH[rt][1], aH[rt][2], aH[rt][3], AhU + off);
            ldsm_x4(aL[rt][0], aL[rt][1], aL[rt][2], aL[rt][3], AlU + off);
        }
        #pragma unroll
        for (int bt = 0; bt < 2; bt++) {
            uint32_t off = (uint32_t)(((wcol + bt * 16) * LDT + ks) * 2) + laneOff;
            uint32_t r0, r1, r2, r3;
            ldsm_x4(r0, r1, r2, r3, BhU + off);
            bH[bt * 2][0] = r0; bH[bt * 2][1] = r2;
            bH[bt * 2 + 1][0] = r1; bH[bt * 2 + 1][1] = r3;
            ldsm_x4(r0, r1, r2, r3, BlU + off);
            bL[bt * 2][0] = r0; bL[bt * 2][1] = r2;
            bL[bt * 2 + 1][0] = r1; bL[bt * 2 + 1][1] = r3;
        }
        #pragma unroll
        for (int rt = 0; rt < 4; rt++)
            #pragma unroll
            for (int ct = 0; ct < 4; ct++) {
                mma_bf16(acc[rt][ct], aH[rt], bH[ct][0], bH[ct][1]);
                mma_bf16(acc[rt][ct], aH[rt], bL[ct][0], bL[ct][1]);
                mma_bf16(acc[rt][ct], aL[rt], bH[ct][0], bH[ct][1]);
            }
    }
}

__device__ __forceinline__ void gemm_mainloop(const uint16_t* Ah, const uint16_t* Al,
                                              const uint16_t* Bh, const uint16_t* Bl,
                                              int row0, int col0, uint32_t S,
                                              float acc[4][4][4]) {
    int tid = threadIdx.x, wid = tid >> 5, lid = tid & 31;
    int wrow = (wid >> 2) * 64, wcol = (wid & 3) * 32;
    uint32_t laneOff = (uint32_t)((((lid & 15) * LDT) + ((lid & 16) ? 8 : 0)) * 2);

    load_chunk_async(S, 0, tid, Ah, Al, Bh, Bl, row0, col0);
    CP_COMMIT();
    for (int ci = 0; ci < 32; ci++) {
        if (ci < 31) {
            load_chunk_async(S + ((ci + 1) & 1) * BUF_BYTES, (ci + 1) * 32, tid,
                             Ah, Al, Bh, Bl, row0, col0);
            CP_COMMIT();
            CP_WAIT1();
        } else {
            CP_WAIT0();
        }
        __syncthreads();
        compute_chunk(S + (ci & 1) * BUF_BYTES, wrow, wcol, laneOff, acc);
        __syncthreads();
    }
}

// ---------------- Q = hs @ Wq^T + bq -> g_q (split bf16) ----------------
__global__ void __launch_bounds__(256) q_mma(const float* __restrict__ bq) {
    extern __shared__ char smem[];
    uint32_t S = smem_u32(smem);
    int row0 = blockIdx.y * 128, col0 = blockIdx.x * 128;
    float acc[4][4][4] = {};
    gemm_mainloop(g_hs_h, g_hs_l, g_w_h, g_w_l, row0, col0, S, acc);

    int tid = threadIdx.x, wid = tid >> 5, lid = tid & 31;
    int gid = lid >> 2, tig = lid & 3;
    int wrow = (wid >> 2) * 64, wcol = (wid & 3) * 32;
    #pragma unroll
    for (int rt = 0; rt < 4; rt++)
        #pragma unroll
        for (int ct = 0; ct < 4; ct++) {
            int d = col0 + wcol + ct * 8 + tig * 2;
            int h = d >> 6, dh = d & 63;
            float b0 = bq[d], b1 = bq[d + 1];
            #pragma unroll
            for (int hf = 0; hf < 2; hf++) {
                int rg = row0 + wrow + rt * 16 + gid + hf * 8;
                int b = rg >> 12, s = rg & 4095;
                uint32_t hh, ll;
                split_pack(acc[rt][ct][hf * 2 + 0] + b0, acc[rt][ct][hf * 2 + 1] + b1, hh, ll);
                size_t idx = (((size_t)b * 16 + h) * 4096 + s) * 64 + dh;
                *(uint32_t*)&g_q_h[idx] = hh;
                *(uint32_t*)&g_q_l[idx] = ll;
            }
        }
}

// ---------------- K/V = (hp @ W^T + cp*bias) * inv -> g_k/g_v (split bf16) --------
__global__ void __launch_bounds__(256) kv_mma(const float* __restrict__ bk,
                                              const float* __restrict__ bv) {
    extern __shared__ char smem[];
    uint32_t S = smem_u32(smem);
    int t = blockIdx.z;
    int row0 = blockIdx.y * 128, col0 = blockIdx.x * 128;
    const float* bias = t ? bv : bk;
    const uint16_t* Ah = g_hp_h + (size_t)t * 2097152;
    const uint16_t* Al = g_hp_l + (size_t)t * 2097152;
    const uint16_t* Bh = g_w_h + (size_t)(1 + t) * 1048576;
    const uint16_t* Bl = g_w_l + (size_t)(1 + t) * 1048576;
    uint16_t* oh = t ? g_v_h : g_k_h;
    uint16_t* ol = t ? g_v_l : g_k_l;

    float acc[4][4][4] = {};
    gemm_mainloop(Ah, Al, Bh, Bl, row0, col0, S, acc);

    int tid = threadIdx.x, wid = tid >> 5, lid = tid & 31;
    int gid = lid >> 2, tig = lid & 3;
    int wrow = (wid >> 2) * 64, wcol = (wid & 3) * 32;
    #pragma unroll
    for (int rt = 0; rt < 4; rt++)
        #pragma unroll
        for (int ct = 0; ct < 4; ct++) {
            int d = col0 + wcol + ct * 8 + tig * 2;
            int h = d >> 6, dh = d & 63;
            float b0 = bias[d], b1 = bias[d + 1];
            #pragma unroll
            for (int hf = 0; hf < 2; hf++) {
                int rg = row0 + wrow + rt * 16 + gid + hf * 8;
                int b = rg >> 8, kk = rg & 255;
                float inv = g_inv[b];
                float cv = g_cp[t * 2048 + b * 256 + kk];
                uint32_t hh, ll;
                split_pack((acc[rt][ct][hf * 2 + 0] + cv * b0) * inv,
                           (acc[rt][ct][hf * 2 + 1] + cv * b1) * inv, hh, ll);
                size_t idx = (((size_t)b * 16 + h) * 256 + kk) * 64 + dh;
                *(uint32_t*)&oh[idx] = hh;
                *(uint32_t*)&ol[idx] = ll;
            }
        }
}

// ---------------- hp = P^T @ hs (masked, pre-split loads) -> g_hp (split) --------
__global__ void __launch_bounds__(256) proj_mma() {
    __shared__ uint16_t sAh[128 * LDT], sAl[128 * LDT], sBh[128 * LDT], sBl[128 * LDT];
    int z = blockIdx.z;
    int t = z >> 3, b = z & 7;
    const uint16_t* ph = g_p_h + (size_t)t * 1048576;
    const uint16_t* pl = g_p_l + (size_t)t * 1048576;
    const uint16_t* hh = g_hs_h + (size_t)b * 4096 * 1024;
    const uint16_t* hl = g_hs_l + (size_t)b * 4096 * 1024;
    int k0 = blockIdx.y * 128, d0 = blockIdx.x * 128;
    int len = g_len[b];

    int tid = threadIdx.x, wid = tid >> 5, lid = tid & 31;
    int wrow = (wid >> 2) * 64, wcol = (wid & 3) * 32;
    uint32_t laneOff = (uint32_t)((((lid & 15) * LDT) + ((lid & 16) ? 8 : 0)) * 2);
    uint32_t AhU = smem_u32(sAh), AlU = smem_u32(sAl);
    uint32_t BhU = smem_u32(sBh), BlU = smem_u32(sBl);

    float acc[4][4][4] = {};

    for (int s0 = 0; s0 < len; s0 += 32) {
        #pragma unroll
        for (int it = 0; it < 4; it++) {
            int lin = it * 256 + tid;
            int s = lin >> 5;
            int c = (lin & 31) * 4;
            bool ok = (s0 + s) < len;
            uint2 ahv = ok ? *(const uint2*)(ph + (size_t)(s0 + s) * 256 + k0 + c) : make_uint2(0, 0);
            uint2 alv = ok ? *(const uint2*)(pl + (size_t)(s0 + s) * 256 + k0 + c) : make_uint2(0, 0);
            uint2 bhv = ok ? *(const uint2*)(hh + (size_t)(s0 + s) * 1024 + d0 + c) : make_uint2(0, 0);
            uint2 blv = ok ? *(const uint2*)(hl + (size_t)(s0 + s) * 1024 + d0 + c) : make_uint2(0, 0);
            uint16_t a4[4] = {(uint16_t)(ahv.x & 0xffff), (uint16_t)(ahv.x >> 16),
                              (uint16_t)(ahv.y & 0xffff), (uint16_t)(ahv.y >> 16)};
            uint16_t a4l[4] = {(uint16_t)(alv.x & 0xffff), (uint16_t)(alv.x >> 16),
                               (uint16_t)(alv.y & 0xffff), (uint16_t)(alv.y >> 16)};
            uint16_t b4[4] = {(uint16_t)(bhv.x & 0xffff), (uint16_t)(bhv.x >> 16),
                              (uint16_t)(bhv.y & 0xffff), (uint16_t)(bhv.y >> 16)};
            uint16_t b4l[4] = {(uint16_t)(blv.x & 0xffff), (uint16_t)(blv.x >> 16),
                               (uint16_t)(blv.y & 0xffff), (uint16_t)(blv.y >> 16)};
            #pragma unroll
            for (int i = 0; i < 4; i++) {
                sAh[(c + i) * LDT + s] = a4[i];
                sAl[(c + i) * LDT + s] = a4l[i];
                sBh[(c + i) * LDT + s] = b4[i];
                sBl[(c + i) * LDT + s] = b4l[i];
            }
        }
        __syncthreads();
        compute_chunk(AhU, wrow, wcol, laneOff, acc);   // works: AhU..BlU contiguous MAT_BYTES apart?
        __syncthreads();
    }

    int gid = lid >> 2, tig = lid & 3;
    #pragma unroll
    for (int rt = 0; rt < 4; rt++)
        #pragma unroll
        for (int ct = 0; ct < 4; ct++) {
            int dd = d0 + wcol + ct * 8 + tig * 2;
            #pragma unroll
            for (int hf = 0; hf < 2; hf++) {
                int rk = k0 + wrow + rt * 16 + gid + hf * 8;
                uint32_t hh2, ll2;
                split_pack(acc[rt][ct][hf * 2 + 0], acc[rt][ct][hf * 2 + 1], hh2, ll2);
                size_t idx = ((size_t)z * 256 + rk) * 1024 + dd;
                *(uint32_t*)&g_hp_h[idx] = hh2;
                *(uint32_t*)&g_hp_l[idx] = ll2;
            }
        }
}

// ---------------- lengths ----------------
__global__ void len_kernel(const float* __restrict__ mask) {
    int b = blockIdx.x;
    int cnt = 0;
    for (int s = threadIdx.x; s < 4096; s += 256)
        cnt += (mask[b * 4096 + s] > -1.0f) ? 1 : 0;
    #pragma unroll
    for (int o = 16; o; o >>= 1) cnt += __shfl_xor_sync(0xffffffffu, cnt, o);
    __shared__ int wsum[8];
    if ((threadIdx.x & 31) == 0) wsum[threadIdx.x >> 5] = cnt;
    __syncthreads();
    if (threadIdx.x == 0) {
        int tot = 0;
        #pragma unroll
        for (int i = 0; i < 8; i++) tot += wsum[i];
        g_len[b] = tot;
        g_inv[b] = rsqrtf((float)tot);
    }
}

// ---------------- masked column sums of proj ----------------
__global__ void cp_kernel(const float* __restrict__ pk, const float* __restrict__ pv) {
    int t = blockIdx.z, b = blockIdx.y, k0 = blockIdx.x * 64;
    const float* p = t ? pv : pk;
    int len = g_len[b];
    int kl = threadIdx.x & 63, sp = threadIdx.x >> 6;
    float sum = 0.f;
    for (int s = sp; s < len; s += 4) sum += p[s * 256 + k0 + kl];
    __shared__ float red[4][64];
    red[sp][kl] = sum;
    __syncthreads();
    if (sp == 0)
        g_cp[(t * 8 + b) * 256 + k0 + kl] =
            red[0][kl] + red[1][kl] + red[2][kl] + red[3][kl];
}

// ---------------- attention via mma ----------------
static constexpr int LQ = 72;
static constexpr int LP = 264;
static constexpr int OFF_QH = 0;
static constexpr int OFF_QL = 9216;
static constexpr int OFF_KH = 18432;
static constexpr int OFF_KL = 55296;
static constexpr int OFF_PH = 0;
static constexpr int OFF_PL = 33792;
static constexpr int OFF_VH = 67584;
static constexpr int OFF_VL = 101376;
static constexpr int OFF_RMAX = 135168;
static constexpr int OFF_RSUM = 137216;
static constexpr int SMEM_ATTN = 139264;

__global__ void __launch_bounds__(256) attn_mma(float* __restrict__ out) {
    extern __shared__ char smem[];
    int s0 = blockIdx.x * 64, h = blockIdx.y, b = blockIdx.z;
    size_t qoff = (((size_t)b * 16 + h) * 4096 + s0) * 64;
    size_t koff = ((size_t)b * 16 + h) * 256 * 64;

    int tid = threadIdx.x, wid = tid >> 5, lid = tid & 31;
    int gid = lid >> 2, tig = lid & 3;
    int qr = lid & 15;
    int qc = (lid & 16) ? 8 : 0;
    uint32_t S = smem_u32(smem);
    float* rmax = (float*)(smem + OFF_RMAX);
    float* rsum = (float*)(smem + OFF_RSUM);

    // ---- Q: 64x64 halves x2 arrays; uint4 copies ----
    #pragma unroll
    for (int it = 0; it < 4; it++) {
        int lin = it * 256 + tid;               // 0..1023
        int arr = lin >> 9;                     // 0:h 1:l
        int s2 = lin & 511;
        int r = s2 >> 3, c = (s2 & 7) * 8;
        const uint16_t* src = (arr ? g_q_l : g_q_h) + qoff + r * 64 + c;
        uint4 v = *(const uint4*)src;
        *(uint4*)(smem + (arr ? OFF_QL : OFF_QH) + (r * LQ + c) * 2) = v;
    }
    // ---- K: 256x64 x2 arrays ----
    #pragma unroll
    for (int it = 0; it < 16; it++) {
        int lin = it * 256 + tid;               // 0..4095
        int arr = lin >> 11;
        int s2 = lin & 2047;
        int r = s2 >> 3, c = (s2 & 7) * 8;
        const uint16_t* src = (arr ? g_k_l : g_k_h) + koff + r * 64 + c;
        uint4 v = *(const uint4*)src;
        *(uint4*)(smem + (arr ? OFF_KL : OFF_KH) + (r * LQ + c) * 2) = v;
    }
    __syncthreads();

    // ---- scores ----
    float acc[4][4][4] = {};
    #pragma unroll
    for (int ks = 0; ks < 64; ks += 16) {
        uint32_t aH[4][4], aL[4][4], bH[4][2], bL[4][2];
        #pragma unroll
        for (int rt = 0; rt < 4; rt++) {
            uint32_t off = (uint32_t)(((rt * 16 + qr) * LQ + ks + qc) * 2);
            ldsm_x4(aH[rt][0], aH[rt][1], aH[rt][2], aH[rt][3], S + OFF_QH + off);
            ldsm_x4(aL[rt][0], aL[rt][1], aL[rt][2], aL[rt][3], S + OFF_QL + off);
        }
        #pragma unroll
        for (int bt = 0; bt < 2; bt++) {
            uint32_t off = (uint32_t)(((wid * 32 + bt * 16 + qr) * LQ + ks + qc) * 2);
            uint32_t r0, r1, r2, r3;
            ldsm_x4(r0, r1, r2, r3, S + OFF_KH + off);
            bH[bt * 2][0] = r0; bH[bt * 2][1] = r2;
            bH[bt * 2 + 1][0] = r1; bH[bt * 2 + 1][1] = r3;
            ldsm_x4(r0, r1, r2, r3, S + OFF_KL + off);
            bL[bt * 2][0] = r0; bL[bt * 2][1] = r2;
            bL[bt * 2 + 1][0] = r1; bL[bt * 2 + 1][1] = r3;
        }
        #pragma unroll
        for (int rt = 0; rt < 4; rt++)
            #pragma unroll
            for (int ct = 0; ct < 4; ct++) {
                mma_bf16(acc[rt][ct], aH[rt], bH[ct][0], bH[ct][1]);
                mma_bf16(acc[rt][ct], aH[rt], bL[ct][0], bL[ct][1]);
                mma_bf16(acc[rt][ct], aL[rt], bH[ct][0], bH[ct][1]);
            }
    }
    __syncthreads();

    // ---- V transposed into VT region ----
    #pragma unroll
    for (int it = 0; it < 16; it++) {
        int lin = it * 256 + tid;
        int arr = lin >> 11;
        int s2 = lin & 2047;
        int k = s2 >> 3, d = (s2 & 7) * 8;
        const uint16_t* src = (arr ? g_v_l : g_v_h) + koff + k * 64 + d;
        uint4 v = *(const uint4*)src;
        char* dstb = smem + (arr ? OFF_VL : OFF_VH);
        uint16_t hv[8] = {(uint16_t)(v.x & 0xffff), (uint16_t)(v.x >> 16),
                          (uint16_t)(v.y & 0xffff), (uint16_t)(v.y >> 16),
                          (uint16_t)(v.z & 0xffff), (uint16_t)(v.z >> 16),
                          (uint16_t)(v.w & 0xffff), (uint16_t)(v.w >> 16)};
        #pragma unroll
        for (int i = 0; i < 8; i++)
            *(uint16_t*)(dstb + ((d + i) * LP + k) * 2) = hv[i];
    }

    // ---- softmax ----
    const float scale = 0.125f;
    float gs[8];
    #pragma unroll
    for (int rt = 0; rt < 4; rt++)
        #pragma unroll
        for (int hf = 0; hf < 2; hf++) {
            float m = -1e30f;
            #pragma unroll
            for (int ct = 0; ct < 4; ct++)
                #pragma unroll
                for (int e = 0; e < 2; e++) {
                    acc[rt][ct][hf * 2 + e] *= scale;
                    m = fmaxf(m, acc[rt][ct][hf * 2 + e]);
                }
            m = fmaxf(m, __shfl_xor_sync(0xffffffffu, m, 1));
            m = fmaxf(m, __shfl_xor_sync(0xffffffffu, m, 2));
            if (tig == 0) rmax[(rt * 16 + gid + hf * 8) * 8 + wid] = m;
        }
    __syncthreads();
    #pragma unroll
    for (int rt = 0; rt < 4; rt++)
        #pragma unroll
        for (int hf = 0; hf < 2; hf++) {
            int row = rt * 16 + gid + hf * 8;
            float m = rmax[row * 8 + 0];
            #pragma unroll
            for (int w = 1; w < 8; w++) m = fmaxf(m, rmax[row * 8 + w]);
            float s = 0.f;
            #pragma unroll
            for (int ct = 0; ct < 4; ct++)
                #pragma unroll
                for (int e = 0; e < 2; e++) {
                    float pv2 = __expf(acc[rt][ct][hf * 2 + e] - m);
                    acc[rt][ct][hf * 2 + e] = pv2;
                    s += pv2;
                }
            s += __shfl_xor_sync(0xffffffffu, s, 1);
            s += __shfl_xor_sync(0xffffffffu, s, 2);
            if (tig == 0) rsum[row * 8 + wid] = s;
        }
    __syncthreads();
    #pragma unroll
    for (int rt = 0; rt < 4; rt++)
        #pragma unroll
        for (int hf = 0; hf < 2; hf++) {
            int row = rt * 16 + gid + hf * 8;
            float s = 0.f;
            #pragma unroll
            for (int w = 0; w < 8; w++) s += rsum[row * 8 + w];
            gs[rt * 2 + hf] = 1.0f / s;
        }

    // ---- probs split to P region ----
    #pragma unroll
    for (int rt = 0; rt < 4; rt++)
        #pragma unroll
        for (int hf = 0; hf < 2; hf++) {
            int row = rt * 16 + gid + hf * 8;
            float rinv = gs[rt * 2 + hf];
            #pragma unroll
            for (int ct = 0; ct < 4; ct++) {
                int col = wid * 32 + ct * 8 + tig * 2;
                uint32_t hh, ll;
                split_pack(acc[rt][ct][hf * 2 + 0] * rinv, acc[rt][ct][hf * 2 + 1] * rinv, hh, ll);
                *(uint32_t*)(smem + OFF_PH + (row * LP + col) * 2) = hh;
                *(uint32_t*)(smem + OFF_PL + (row * LP + col) * 2) = ll;
            }
        }
    __syncthreads();

    // ---- ctx = P @ VT^T ----
    float acc2[2][2][4] = {};
    int arow = (wid >> 2) * 32;
    int bcol = (wid & 3) * 16;
    #pragma unroll
    for (int ks = 0; ks < 256; ks += 16) {
        uint32_t aH[2][4], aL[2][4], bH[2][2], bL[2][2];
        #pragma unroll
        for (int rt = 0; rt < 2; rt++) {
            uint32_t off = (uint32_t)(((arow + rt * 16 + qr) * LP + ks + qc) * 2);
            ldsm_x4(aH[rt][0], aH[rt][1], aH[rt][2], aH[rt][3], S + OFF_PH + off);
            ldsm_x4(aL[rt][0], aL[rt][1], aL[rt][2], aL[rt][3], S + OFF_PL + off);
        }
        {
            uint32_t off = (uint32_t)(((bcol + qr) * LP + ks + qc) * 2);
            uint32_t r0, r1, r2, r3;
            ldsm_x4(r0, r1, r2, r3, S + OFF_VH + off);
            bH[0][0] = r0; bH[0][1] = r2;
            bH[1][0] = r1; bH[1][1] = r3;
            ldsm_x4(r0, r1, r2, r3, S + OFF_VL + off);
            bL[0][0] = r0; bL[0][1] = r2;
            bL[1][0] = r1; bL[1][1] = r3;
        }
        #pragma unroll
        for (int rt = 0; rt < 2; rt++)
            #pragma unroll
            for (int cg = 0; cg < 2; cg++) {
                mma_bf16(acc2[rt][cg], aH[rt], bH[cg][0], bH[cg][1]);
                mma_bf16(acc2[rt][cg], aH[rt], bL[cg][0], bL[cg][1]);
                mma_bf16(acc2[rt][cg], aL[rt], bH[cg][0], bH[cg][1]);
            }
    }

    #pragma unroll
    for (int rt = 0; rt < 2; rt++)
        #pragma unroll
        for (int cg = 0; cg < 2; cg++) {
            int col = bcol + cg * 8 + tig * 2;
            #pragma unroll
            for (int hf = 0; hf < 2; hf++) {
                int row = arow + rt * 16 + gid + hf * 8;
                float2 o = {acc2[rt][cg][hf * 2 + 0], acc2[rt][cg][hf * 2 + 1]};
                *(float2*)&out[((size_t)b * 4096 + s0 + row) * 1024 + h * 64 + col] = o;
            }
        }
}

// ---------------- launch ----------------
extern "C" void kernel_launch(void* const* d_in, const int* in_sizes, int n_in,
                              void* d_out, int out_size) {
    const float* hs   = (const float*)d_in[0];
    const float* mask = (const float*)d_in[1];
    const float* bq   = (const float*)d_in[3];
    const float* bk   = (const float*)d_in[5];
    const float* bv   = (const float*)d_in[7];
    const float* Wq   = (const float*)d_in[2];
    const float* Wk   = (const float*)d_in[4];
    const float* Wv   = (const float*)d_in[6];
    const float* pk   = (const float*)d_in[8];
    const float* pv   = (const float*)d_in[9];
    float* out = (float*)d_out;

    cudaFuncSetAttribute(q_mma,   cudaFuncAttributeMaxDynamicSharedMemorySize, SMEM_GEMM);
    cudaFuncSetAttribute(kv_mma,  cudaFuncAttributeMaxDynamicSharedMemorySize, SMEM_GEMM);
    cudaFuncSetAttribute(attn_mma, cudaFuncAttributeMaxDynamicSharedMemorySize, SMEM_ATTN);

    len_kernel<<<8, 256>>>(mask);
    cp_kernel<<<dim3(4, 8, 2), 256>>>(pk, pv);
    conv_kernel<<<32768, 256>>>((const float4*)hs, 0, 8388608);
    conv_kernel<<<1024, 256>>>((const float4*)pk, 1, 262144);
    conv_kernel<<<1024, 256>>>((const float4*)pv, 2, 262144);
    conv_kernel<<<1024, 256>>>((const float4*)Wq, 3, 262144);
    conv_kernel<<<1024, 256>>>((const float4*)Wk, 4, 262144);
    conv_kernel<<<1024, 256>>>((const float4*)Wv, 5, 262144);
    proj_mma<<<dim3(8, 2, 16), 256>>>();
    kv_mma<<<dim3(8, 16, 2), 256, SMEM_GEMM>>>(bk, bv);
    q_mma<<<dim3(8, 256), 256, SMEM_GEMM>>>(bq);
    attn_mma<<<dim3(64, 16, 8), 256, SMEM_ATTN>>>(out);
}